// round 10
// baseline (speedup 1.0000x reference)
#include <cuda_runtime.h>
#include <math.h>

#define NQB 4
#define BB  512
#define SS  256
#define DD  64
#define HH  128
#define FULL 0xffffffffu

__device__ __forceinline__ float2 cmul(float2 a, float2 b) {
    return make_float2(fmaf(a.x, b.x, -a.y * b.y), fmaf(a.x, b.y, a.y * b.x));
}
__device__ __forceinline__ float tanha(float x) {
    float r;
    asm("tanh.approx.f32 %0, %1;" : "=f"(r) : "f"(x));
    return r;
}

// source index after the CNOT ring (0,1)(1,2)(2,3)(3,0), gather form
__device__ __forceinline__ int cnot_src(int i) {
    i ^= (i & 1) ? 8 : 0;   // CNOT(3,0)
    i ^= (i & 2) ? 1 : 0;   // CNOT(2,3)
    i ^= (i & 4) ? 2 : 0;   // CNOT(1,2)
    i ^= (i & 8) ? 4 : 0;   // CNOT(0,1)
    return i;
}

__global__ __launch_bounds__(128)
void qlstm_kernel(const float* __restrict__ x,
                  const float* __restrict__ W_in,
                  const float* __restrict__ b_in,
                  const float* __restrict__ W_out,
                  const float* __restrict__ b_out,
                  const float* __restrict__ w_f,
                  const float* __restrict__ w_i,
                  const float* __restrict__ w_u,
                  const float* __restrict__ w_o,
                  float* __restrict__ out,
                  int write_tails)
{
    __shared__ __align__(16) float sZ[2][4][4];   // double-buffered [gate][qubit] <Z>

    const int tid  = threadIdx.x;
    const int lane = tid & 31;
    const int wid  = tid >> 5;          // warp = gate: 0=f 1=i 2=u 3=o
    const int il   = lane & 15;         // amplitude index (lanes 16-31 mirror)
    const int b    = blockIdx.x;

    // ---- per-lane constants (registers only) ----
    // this lane owns h-dims {lane+32r} and x-dims {2*lane, 2*lane+1}
    float4 wiH[4];
    #pragma unroll
    for (int r = 0; r < 4; ++r)
        wiH[r] = *(const float4*)(W_in + 4 * (lane + 32 * r));
    float4 wx0 = *(const float4*)(W_in + 4 * (HH + 2 * lane));
    float4 wx1 = *(const float4*)(W_in + 4 * (HH + 2 * lane + 1));
    float4 binv = *(const float4*)(b_in);
    // halved projection weights: sigmoid(a)=0.5+0.5*tanh(a/2), tanh(a)=tanh(2*(a/2))
    float wo[NQB][4], bo[4];
    #pragma unroll
    for (int j = 0; j < NQB; ++j)
        #pragma unroll
        for (int r = 0; r < 4; ++r)
            wo[j][r] = 0.5f * W_out[j * HH + lane + 32 * r];
    #pragma unroll
    for (int r = 0; r < 4; ++r) bo[r] = 0.5f * b_out[lane + 32 * r];

    bool  hqv[NQB];
    float hsv[NQB];
    #pragma unroll
    for (int q = 0; q < NQB; ++q) {
        hqv[q] = (il >> (3 - q)) & 1;
        hsv[q] = hqv[q] ? 0.5f : -0.5f;
    }

    // fused ansatz U = RZ*RY*RX for THIS warp's gate; keep the row this lane needs
    float2 av0[NQB], av1[NQB];
    {
        const float* wg = (wid == 0) ? w_f : (wid == 1) ? w_i : (wid == 2) ? w_u : w_o;
        #pragma unroll
        for (int q = 0; q < NQB; ++q) {
            float sa, ca, sb, cb, sg, cg;
            sincosf(wg[q]           * 0.5f, &sa, &ca);
            sincosf(wg[NQB + q]     * 0.5f, &sb, &cb);
            sincosf(wg[2 * NQB + q] * 0.5f, &sg, &cg);
            float2 m00 = make_float2( cb * ca,  sb * sa);
            float2 m01 = make_float2(-sb * ca, -cb * sa);
            float2 m10 = make_float2( sb * ca, -cb * sa);
            float2 m11 = make_float2( cb * ca, -sb * sa);
            float2 e0  = make_float2(cg, -sg);
            float2 e1  = make_float2(cg,  sg);
            if (hqv[q]) { av0[q] = cmul(e1, m10); av1[q] = cmul(e1, m11); }
            else        { av0[q] = cmul(e0, m00); av1[q] = cmul(e0, m01); }
        }
    }

    const int src0 = cnot_src(il & 7);   // bit8=0 partner, CNOT-ring fused
    const int src1 = cnot_src(il | 8);   // bit8=1 partner

    const bool rb16 = (lane & 16) != 0;
    const bool rb8  = (lane & 8)  != 0;
    const bool isWriterZ = (lane < 16) && (__popc(il) == 1);
    const int  zj        = 4 - __ffs(il);        // lane 8->q0, 4->q1, 2->q2, 1->q3

    const float* xb = x + (size_t)b * SS * DD;
    float2 xv = *(const float2*)(xb + 2 * lane);

    float h[4] = {0.f, 0.f, 0.f, 0.f};
    float c[4] = {0.f, 0.f, 0.f, 0.f};
    float* op = out + (size_t)b * SS * HH + 32 * wid + lane;   // warp writes its quarter

    for (int t = 0; t < SS; ++t) {
        // ---- 1. y = [h, x_t] @ W_in + b_in, fully warp-local ----
        float p0 = fmaf(xv.y, wx1.x, xv.x * wx0.x);
        float p1 = fmaf(xv.y, wx1.y, xv.x * wx0.y);
        float p2 = fmaf(xv.y, wx1.z, xv.x * wx0.z);
        float p3 = fmaf(xv.y, wx1.w, xv.x * wx0.w);
        #pragma unroll
        for (int r = 0; r < 4; ++r) {
            p0 = fmaf(h[r], wiH[r].x, p0);
            p1 = fmaf(h[r], wiH[r].y, p1);
            p2 = fmaf(h[r], wiH[r].z, p2);
            p3 = fmaf(h[r], wiH[r].w, p3);
        }
        if (t + 1 < SS) xv = *(const float2*)(xb + (t + 1) * DD + 2 * lane);

        // reduce-scatter butterfly: group (b16,b8) ends holding y_{2b16+b8}
        float t0 = rb16 ? p0 : p2;
        t0 = __shfl_xor_sync(FULL, t0, 16);
        float ra = (rb16 ? p2 : p0) + t0;
        float t1 = rb16 ? p1 : p3;
        t1 = __shfl_xor_sync(FULL, t1, 16);
        float rbv = (rb16 ? p3 : p1) + t1;
        float t2s = rb8 ? ra : rbv;
        t2s = __shfl_xor_sync(FULL, t2s, 8);
        float k = (rb8 ? rbv : ra) + t2s;
        k += __shfl_xor_sync(FULL, k, 4);
        k += __shfl_xor_sync(FULL, k, 2);
        k += __shfl_xor_sync(FULL, k, 1);
        // broadcast all four sums to every lane
        float yv[NQB];
        yv[0] = __shfl_sync(FULL, k, 0)  + binv.x;
        yv[1] = __shfl_sync(FULL, k, 8)  + binv.y;
        yv[2] = __shfl_sync(FULL, k, 16) + binv.z;
        yv[3] = __shfl_sync(FULL, k, 24) + binv.w;

        // ---- 2. encoding product state, combined-normalization form ----
        float2 amp;
        {
            float P = 1.f, Dm = 1.f;
            float zx = 1.f, zy = 0.f;
            #pragma unroll
            for (int q = 0; q < NQB; ++q) {
                float y  = yv[q];
                float t2 = y * y;
                float r  = rsqrtf(1.f + t2);             // MUFU
                float s  = y * r;                        // sin(atan y)
                float x2 = fmaf(hsv[q], s, 0.5f);
                P *= x2;
                float tq = hqv[q] ? t2 : 0.f;
                float nzx = fmaf(-zy, tq, zx);
                float nzy = fmaf( zx, tq, zy);
                zx = nzx; zy = nzy;
                Dm *= fmaf(tq, tq, 1.f);
            }
            float m = P * rsqrtf(P * Dm);                // sqrt(P/D), 1 MUFU
            amp = make_float2(zx * m, zy * m);
        }

        // ---- 3. ansatz: gate 0 fused with CNOT ring permutation ----
        float2 a0, a1;
        a0.x = __shfl_sync(FULL, amp.x, src0, 16);
        a0.y = __shfl_sync(FULL, amp.y, src0, 16);
        a1.x = __shfl_sync(FULL, amp.x, src1, 16);
        a1.y = __shfl_sync(FULL, amp.y, src1, 16);

        float2 cur;
        {
            float2 u0 = av0[0], u1 = av1[0];
            cur.x = u0.x*a0.x - u0.y*a0.y + u1.x*a1.x - u1.y*a1.y;
            cur.y = u0.x*a0.y + u0.y*a0.x + u1.x*a1.y + u1.y*a1.x;
        }
        #pragma unroll
        for (int q = 1; q < NQB; ++q) {
            const int  m  = 8 >> q;
            const bool hi = hqv[q];
            float ox = __shfl_xor_sync(FULL, cur.x, m, 16);
            float oy = __shfl_xor_sync(FULL, cur.y, m, 16);
            float a0x = hi ? ox : cur.x, a0y = hi ? oy : cur.y;
            float a1x = hi ? cur.x : ox, a1y = hi ? cur.y : oy;
            float2 u0 = av0[q], u1 = av1[q];
            cur.x = u0.x*a0x - u0.y*a0y + u1.x*a1x - u1.y*a1y;
            cur.y = u0.x*a0y + u0.y*a0x + u1.x*a1y + u1.y*a1x;
        }

        // ---- 4. <Z_q> via 4-level Walsh-Hadamard, publish (double-buffered) ----
        float w0 = cur.x * cur.x + cur.y * cur.y;
        #pragma unroll
        for (int m = 8; m; m >>= 1) {
            float o = __shfl_xor_sync(FULL, w0, m, 16);
            w0 = (il & m) ? (o - w0) : (w0 + o);
        }
        const int buf = t & 1;
        if (isWriterZ) sZ[buf][wid][zj] = w0;
        __syncthreads();                 // the ONLY barrier per step

        // ---- 5. projection + LSTM, replicated across warps (4 dims/lane) ----
        float4 z0 = *(const float4*)sZ[buf][0];
        float4 z1 = *(const float4*)sZ[buf][1];
        float4 z2 = *(const float4*)sZ[buf][2];
        float4 z3 = *(const float4*)sZ[buf][3];
        float hout = 0.f;
        #pragma unroll
        for (int r = 0; r < 4; ++r) {
            float af = fmaf(z0.x, wo[0][r], fmaf(z0.y, wo[1][r], fmaf(z0.z, wo[2][r], fmaf(z0.w, wo[3][r], bo[r]))));
            float ai = fmaf(z1.x, wo[0][r], fmaf(z1.y, wo[1][r], fmaf(z1.z, wo[2][r], fmaf(z1.w, wo[3][r], bo[r]))));
            float ag = fmaf(z2.x, wo[0][r], fmaf(z2.y, wo[1][r], fmaf(z2.z, wo[2][r], fmaf(z2.w, wo[3][r], bo[r]))));
            float ao = fmaf(z3.x, wo[0][r], fmaf(z3.y, wo[1][r], fmaf(z3.z, wo[2][r], fmaf(z3.w, wo[3][r], bo[r]))));
            float f = fmaf(0.5f, tanha(af), 0.5f);
            float i = fmaf(0.5f, tanha(ai), 0.5f);
            float g = tanha(ag + ag);
            float o = fmaf(0.5f, tanha(ao), 0.5f);
            c[r] = fmaf(f, c[r], i * g);
            h[r] = o * tanha(c[r]);
            if (r == wid) hout = h[r];
        }
        *op = hout;
        op += HH;
    }

    if (write_tails) {
        size_t base = (size_t)BB * SS * HH;
        float hout = (wid == 0) ? h[0] : (wid == 1) ? h[1] : (wid == 2) ? h[2] : h[3];
        float cout = (wid == 0) ? c[0] : (wid == 1) ? c[1] : (wid == 2) ? c[2] : c[3];
        out[base + (size_t)b * HH + 32 * wid + lane] = hout;
        out[base + (size_t)BB * HH + (size_t)b * HH + 32 * wid + lane] = cout;
    }
}

extern "C" void kernel_launch(void* const* d_in, const int* in_sizes, int n_in,
                              void* d_out, int out_size) {
    const float* x     = (const float*)d_in[0];
    const float* W_in  = (const float*)d_in[1];
    const float* b_in  = (const float*)d_in[2];
    const float* W_out = (const float*)d_in[3];
    const float* b_out = (const float*)d_in[4];
    const float* w_f   = (const float*)d_in[5];
    const float* w_i   = (const float*)d_in[6];
    const float* w_u   = (const float*)d_in[7];
    const float* w_o   = (const float*)d_in[8];
    float* out = (float*)d_out;

    int need_tail = (size_t)out_size >= (size_t)BB * SS * HH + 2 * (size_t)BB * HH;
    qlstm_kernel<<<BB, HH>>>(x, W_in, b_in, W_out, b_out,
                             w_f, w_i, w_u, w_o, out, need_tail);
}

// round 12
// speedup vs baseline: 1.4385x; 1.4385x over previous
#include <cuda_runtime.h>
#include <math.h>

#define NQB 4
#define BB  512
#define SS  256
#define DD  64
#define HH  128
#define FULL 0xffffffffu

#define YSCALE  4194304.0f        // 2^22
#define YINV    (1.0f / 4194304.0f)
#define ZSCALE  67108864.0f       // 2^26
#define ZINV    (1.0f / 67108864.0f)

__device__ __forceinline__ float2 cmul(float2 a, float2 b) {
    return make_float2(fmaf(a.x, b.x, -a.y * b.y), fmaf(a.x, b.y, a.y * b.x));
}
__device__ __forceinline__ float tanha(float x) {
    float r;
    asm("tanh.approx.f32 %0, %1;" : "=f"(r) : "f"(x));
    return r;
}
// warp-wide s32 add reduction (sm_80+), result in all lanes
__device__ __forceinline__ int redux_add_s32(int v) {
    int r;
    asm("redux.sync.add.s32 %0, %1, 0xffffffff;" : "=r"(r) : "r"(v));
    return r;
}

// source index after the CNOT ring (0,1)(1,2)(2,3)(3,0), gather form
__device__ __forceinline__ int cnot_src(int i) {
    i ^= (i & 1) ? 8 : 0;   // CNOT(3,0)
    i ^= (i & 2) ? 1 : 0;   // CNOT(2,3)
    i ^= (i & 4) ? 2 : 0;   // CNOT(1,2)
    i ^= (i & 8) ? 4 : 0;   // CNOT(0,1)
    return i;
}

__global__ __launch_bounds__(128)
void qlstm_kernel(const float* __restrict__ x,
                  const float* __restrict__ W_in,
                  const float* __restrict__ b_in,
                  const float* __restrict__ W_out,
                  const float* __restrict__ b_out,
                  const float* __restrict__ w_f,
                  const float* __restrict__ w_i,
                  const float* __restrict__ w_u,
                  const float* __restrict__ w_o,
                  float* __restrict__ out,
                  int write_tails)
{
    __shared__ __align__(16) int4   sP[4];   // [warp] -> int y partials (scaled 2^22)
    __shared__ __align__(16) float4 sZ[4];   // [gate] -> <Z_q> floats (scaled 2*2^26)

    const int tid  = threadIdx.x;
    const int lane = tid & 31;
    const int wid  = tid >> 5;          // warp = gate: 0=f 1=i 2=u 3=o
    const int il   = lane & 15;         // amplitude index (lanes 16-31 mirror)
    const int b    = blockIdx.x;

    // ---- per-thread constants (registers) ----
    float4 wi = *(const float4*)(W_in + 4 * tid);                 // W_in row for h-dim tid
    float4 wx = make_float4(0.f, 0.f, 0.f, 0.f);
    if (tid < DD) wx = *(const float4*)(W_in + 4 * (HH + tid));   // W_in row for x-dim tid
    float4 binv = *(const float4*)(b_in);
    // wo scaled by 0.5 (tanh half-angle) * 0.5 (mirror double-count) * 1/2^26 (z fixed-point)
    const float ws = 0.25f * ZINV;
    float wo0 = ws * W_out[tid];
    float wo1 = ws * W_out[HH + tid];
    float wo2 = ws * W_out[2 * HH + tid];
    float wo3 = ws * W_out[3 * HH + tid];
    float bo  = 0.5f * b_out[tid];

    bool  hq[NQB];
    float hs[NQB];
    #pragma unroll
    for (int q = 0; q < NQB; ++q) {
        hq[q] = (il >> (3 - q)) & 1;
        hs[q] = hq[q] ? 0.5f : -0.5f;
    }

    // fused ansatz U = RZ*RY*RX for THIS warp's gate; keep the row this lane needs
    float2 av0[NQB], av1[NQB];
    {
        const float* wg = (wid == 0) ? w_f : (wid == 1) ? w_i : (wid == 2) ? w_u : w_o;
        #pragma unroll
        for (int q = 0; q < NQB; ++q) {
            float sa, ca, sb, cb, sg, cg;
            sincosf(wg[q]           * 0.5f, &sa, &ca);
            sincosf(wg[NQB + q]     * 0.5f, &sb, &cb);
            sincosf(wg[2 * NQB + q] * 0.5f, &sg, &cg);
            float2 m00 = make_float2( cb * ca,  sb * sa);
            float2 m01 = make_float2(-sb * ca, -cb * sa);
            float2 m10 = make_float2( sb * ca, -cb * sa);
            float2 m11 = make_float2( cb * ca, -sb * sa);
            float2 e0  = make_float2(cg, -sg);
            float2 e1  = make_float2(cg,  sg);
            if (hq[q]) { av0[q] = cmul(e1, m10); av1[q] = cmul(e1, m11); }
            else       { av0[q] = cmul(e0, m00); av1[q] = cmul(e0, m01); }
        }
    }

    const int src0 = cnot_src(il & 7);   // bit8=0 partner, CNOT-ring fused
    const int src1 = cnot_src(il | 8);   // bit8=1 partner

    const float* xb = x + (size_t)b * SS * DD;
    float xv = (tid < DD) ? xb[tid] : 0.f;

    float h = 0.f, c = 0.f;
    float* op = out + (size_t)b * SS * HH + tid;

    for (int t = 0; t < SS; ++t) {
        // ---- 1. y = [h, x_t] @ W_in + b_in (fixed-point redux + smem combine) ----
        float p0 = fmaf(h, wi.x, xv * wx.x);
        float p1 = fmaf(h, wi.y, xv * wx.y);
        float p2 = fmaf(h, wi.z, xv * wx.z);
        float p3 = fmaf(h, wi.w, xv * wx.w);
        if (tid < DD && t + 1 < SS) xv = xb[(t + 1) * DD + tid];   // prefetch

        int i0 = redux_add_s32(__float2int_rn(p0 * YSCALE));
        int i1 = redux_add_s32(__float2int_rn(p1 * YSCALE));
        int i2 = redux_add_s32(__float2int_rn(p2 * YSCALE));
        int i3 = redux_add_s32(__float2int_rn(p3 * YSCALE));
        if (lane == 0) sP[wid] = make_int4(i0, i1, i2, i3);
        __syncthreads();

        int4 q0 = sP[0], q1 = sP[1], q2 = sP[2], q3 = sP[3];
        float yv[NQB];
        yv[0] = fmaf(__int2float_rn(q0.x + q1.x + q2.x + q3.x), YINV, binv.x);
        yv[1] = fmaf(__int2float_rn(q0.y + q1.y + q2.y + q3.y), YINV, binv.y);
        yv[2] = fmaf(__int2float_rn(q0.z + q1.z + q2.z + q3.z), YINV, binv.z);
        yv[3] = fmaf(__int2float_rn(q0.w + q1.w + q2.w + q3.w), YINV, binv.w);

        // ---- 2. encoding product state, combined-normalization form ----
        // amp = z * sqrt(P/D), z = prod(1, t2[hi]), P = prod x2, D = prod(1+t4[hi])
        float2 amp;
        {
            float P = 1.f, Dm = 1.f;
            float zx = 1.f, zy = 0.f;
            #pragma unroll
            for (int q = 0; q < NQB; ++q) {
                float y  = yv[q];
                float t2 = y * y;
                float r  = rsqrtf(1.f + t2);             // MUFU
                float s  = y * r;                        // sin(atan y)
                float x2 = fmaf(hs[q], s, 0.5f);
                P *= x2;
                float tq = hq[q] ? t2 : 0.f;
                float nzx = fmaf(-zy, tq, zx);
                float nzy = fmaf( zx, tq, zy);
                zx = nzx; zy = nzy;
                Dm *= fmaf(tq, tq, 1.f);
            }
            float m = P * rsqrtf(P * Dm);                // sqrt(P/D), 1 MUFU
            amp = make_float2(zx * m, zy * m);
        }

        // ---- 3. ansatz: gate 0 fused with CNOT ring permutation ----
        float2 a0, a1;
        a0.x = __shfl_sync(FULL, amp.x, src0, 16);
        a0.y = __shfl_sync(FULL, amp.y, src0, 16);
        a1.x = __shfl_sync(FULL, amp.x, src1, 16);
        a1.y = __shfl_sync(FULL, amp.y, src1, 16);

        float2 cur;
        {
            float2 u0 = av0[0], u1 = av1[0];
            cur.x = u0.x*a0.x - u0.y*a0.y + u1.x*a1.x - u1.y*a1.y;
            cur.y = u0.x*a0.y + u0.y*a0.x + u1.x*a1.y + u1.y*a1.x;
        }
        #pragma unroll
        for (int q = 1; q < NQB; ++q) {
            const int  m  = 8 >> q;
            const bool hi = hq[q];
            float ox = __shfl_xor_sync(FULL, cur.x, m, 16);
            float oy = __shfl_xor_sync(FULL, cur.y, m, 16);
            float a0x = hi ? ox : cur.x, a0y = hi ? oy : cur.y;
            float a1x = hi ? cur.x : ox, a1y = hi ? cur.y : oy;
            float2 u0 = av0[q], u1 = av1[q];
            cur.x = u0.x*a0x - u0.y*a0y + u1.x*a1x - u1.y*a1y;
            cur.y = u0.x*a0y + u0.y*a0x + u1.x*a1y + u1.y*a1x;
        }

        // ---- 4. <Z_q> via signed fixed-point redux (result = 2*2^26*z_true) ----
        float p = cur.x * cur.x + cur.y * cur.y;
        int ip = __float2int_rn(p * ZSCALE);
        int in = -ip;
        int z0 = redux_add_s32((il & 8) ? in : ip);
        int z1 = redux_add_s32((il & 4) ? in : ip);
        int z2 = redux_add_s32((il & 2) ? in : ip);
        int z3 = redux_add_s32((il & 1) ? in : ip);
        if (lane == 0)
            sZ[wid] = make_float4(__int2float_rn(z0), __int2float_rn(z1),
                                  __int2float_rn(z2), __int2float_rn(z3));
        __syncthreads();

        // ---- 5. projection + LSTM cell (one hidden dim per thread) ----
        float4 zf = sZ[0], zi = sZ[1], zu = sZ[2], zo = sZ[3];
        float af = fmaf(zf.x, wo0, fmaf(zf.y, wo1, fmaf(zf.z, wo2, fmaf(zf.w, wo3, bo))));
        float ai = fmaf(zi.x, wo0, fmaf(zi.y, wo1, fmaf(zi.z, wo2, fmaf(zi.w, wo3, bo))));
        float ag = fmaf(zu.x, wo0, fmaf(zu.y, wo1, fmaf(zu.z, wo2, fmaf(zu.w, wo3, bo))));
        float ao = fmaf(zo.x, wo0, fmaf(zo.y, wo1, fmaf(zo.z, wo2, fmaf(zo.w, wo3, bo))));
        float f = fmaf(0.5f, tanha(af), 0.5f);
        float i = fmaf(0.5f, tanha(ai), 0.5f);
        float g = tanha(ag + ag);
        float o = fmaf(0.5f, tanha(ao), 0.5f);
        c = fmaf(f, c, i * g);
        h = o * tanha(c);

        *op = h;
        op += HH;
    }

    if (write_tails) {
        size_t base = (size_t)BB * SS * HH;
        out[base + (size_t)b * HH + tid] = h;
        out[base + (size_t)BB * HH + (size_t)b * HH + tid] = c;
    }
}

extern "C" void kernel_launch(void* const* d_in, const int* in_sizes, int n_in,
                              void* d_out, int out_size) {
    const float* x     = (const float*)d_in[0];
    const float* W_in  = (const float*)d_in[1];
    const float* b_in  = (const float*)d_in[2];
    const float* W_out = (const float*)d_in[3];
    const float* b_out = (const float*)d_in[4];
    const float* w_f   = (const float*)d_in[5];
    const float* w_i   = (const float*)d_in[6];
    const float* w_u   = (const float*)d_in[7];
    const float* w_o   = (const float*)d_in[8];
    float* out = (float*)d_out;

    int need_tail = (size_t)out_size >= (size_t)BB * SS * HH + 2 * (size_t)BB * HH;
    qlstm_kernel<<<BB, HH>>>(x, W_in, b_in, W_out, b_out,
                             w_f, w_i, w_u, w_o, out, need_tail);
}